// round 6
// baseline (speedup 1.0000x reference)
#include <cuda_runtime.h>

#define TAPS 343
typedef unsigned long long ull;

// phase-split s, channel-interleaved: [n][pz][py][px][32][32][32][c4]  (64 MB)
__device__ float g_s[16*8*32*32*32*4];
// phase-split v, channel-interleaved: [n][pz][py][px][17][17][17][c24] (60.4 MB)
__device__ float g_v[16*8*17*17*17*24];
// y pre-BN: [n][16][19][19][19] (7 MB)
__device__ float g_y[16*16*19*19*19];
__device__ float g_sum[16];
__device__ float g_sumsq[16];
__device__ float g_zero[32];   // zero-initialized guard for OOB taps (never written)

__device__ __forceinline__ ull pk(float lo, float hi) {
    ull r; asm("mov.b64 %0,{%1,%2};" : "=l"(r) : "f"(lo), "f"(hi)); return r;
}
__device__ __forceinline__ void unpk(ull v, float& lo, float& hi) {
    asm("mov.b64 {%0,%1},%2;" : "=f"(lo), "=f"(hi) : "l"(v));
}
__device__ __forceinline__ void fma2(ull& d, ull a, ull b) {
    asm("fma.rn.f32x2 %0,%1,%2,%0;" : "+l"(d) : "l"(a), "l"(b));
}
__device__ __forceinline__ ull mul2(ull a, ull b) {
    ull r; asm("mul.rn.f32x2 %0,%1,%2;" : "=l"(r) : "l"(a), "l"(b)); return r;
}

__global__ void k_zero() {
    int i = threadIdx.x;
    if (i < 16) { g_sum[i] = 0.f; g_sumsq[i] = 0.f; }
}

// repack s (NCDHW 64^3) into parity-split channel-interleaved layout.
__global__ void k_split(const float* __restrict__ s) {
    int i = blockIdx.x * 256 + threadIdx.x;          // 2^24 total
    int x = i & 63;
    int y = (i >> 6) & 63;
    int z = (i >> 12) & 63;
    int c = (i >> 18) & 3;
    int n = i >> 20;
    int pp = (((n * 2 + (z & 1)) * 2 + (y & 1)) * 2 + (x & 1));
    int sp = ((z >> 1) * 32 + (y >> 1)) * 32 + (x >> 1);
    g_s[(pp * 32768 + sp) * 4 + c] = s[i];
}

// conv1: s[4ch] -> 36 basis responses -> mix W1 -> v[24ch] interleaved.
// Block tile: 8(ox) x 4(oy) x 8(oz); 128 threads, 2 oz positions per thread,
// packed as (lo,hi) lanes of f32x2.
__global__ __launch_bounds__(128) void k_conv1(const float* __restrict__ basis1,
                                               const float* __restrict__ W1) {
    __shared__ float kb[TAPS * 12];   // [tap][f=0..8, pad 3]
    __shared__ float w1[96];
    int tid = threadIdx.x;
    for (int i = tid; i < TAPS * 12; i += 128) {
        int tap = i / 12, f = i % 12;
        kb[i] = (f < 9) ? basis1[f * TAPS + tap] : 0.f;
    }
    if (tid < 96) w1[tid] = W1[tid];
    __syncthreads();

    int bx = blockIdx.x;                  // grid.x = 5(x)*9(y)*5(z) = 225
    int txi = bx % 5, tyi = (bx / 5) % 9, tzi = bx / 45;
    int n = blockIdx.y;
    int lx = tid & 7, ly = (tid >> 3) & 3, lz = tid >> 5;
    int ox = txi * 8 + lx, oy = tyi * 4 + ly, oz = tzi * 8 + lz;

    ull ACC[36];                         // [c][f], lo = pos A (oz), hi = pos B (oz+4)
#pragma unroll
    for (int i = 0; i < 36; i++) ACC[i] = 0ULL;

    const float4* zb = (const float4*)g_zero;
    int bxx = 2 * ox - 5, byy = 2 * oy - 5, bzz = 2 * oz - 5;
    for (int kz = 0; kz < 7; kz++) {
        int iz = bzz + kz;
        int pz = iz & 1, z2 = iz >> 1;
        bool vzA = (unsigned)z2 < 32u;
        bool vzB = (unsigned)(z2 + 4) < 32u;
        for (int ky = 0; ky < 7; ky++) {
            int iy = byy + ky;
            int py = iy & 1, y2 = iy >> 1;
            bool vy = (unsigned)y2 < 32u;
            int tapzy = (kz * 7 + ky) * 7;
#pragma unroll
            for (int kx = 0; kx < 7; kx++) {
                int ix = bxx + kx;
                int px = ix & 1, x2 = ix >> 1;
                bool vx = (unsigned)x2 < 32u;
                int tap = tapzy + kx;
                float kr[12];
                const float4* kb4 = (const float4*)(kb + tap * 12);
                ((float4*)kr)[0] = kb4[0];
                ((float4*)kr)[1] = kb4[1];
                ((float4*)kr)[2] = kb4[2];
                int pbase = ((n * 2 + pz) * 2 + py) * 2 + px;
                int sp = (z2 * 32 + y2) * 32 + x2;
                const float4* pS = (const float4*)g_s + (pbase * 32768 + sp);
                const float4* pA = (vzA && vy && vx) ? pS        : zb;
                const float4* pB = (vzB && vy && vx) ? pS + 4096 : zb;
                float4 fA = *pA;
                float4 fB = *pB;
                ull sp0 = pk(fA.x, fB.x), sp1 = pk(fA.y, fB.y);
                ull sp2 = pk(fA.z, fB.z), sp3 = pk(fA.w, fB.w);
                ull kd[9];
#pragma unroll
                for (int f = 0; f < 9; f++) kd[f] = pk(kr[f], kr[f]);
#pragma unroll
                for (int f = 0; f < 9; f++) {
                    fma2(ACC[f],      sp0, kd[f]);
                    fma2(ACC[9 + f],  sp1, kd[f]);
                    fma2(ACC[18 + f], sp2, kd[f]);
                    fma2(ACC[27 + f], sp3, kd[f]);
                }
            }
        }
    }

    float acc2[2][36];
#pragma unroll
    for (int i = 0; i < 36; i++) unpk(ACC[i], acc2[0][i], acc2[1][i]);

    // mix (24 out = sum over v,b of W1 * basis response) and store interleaved v
#pragma unroll
    for (int pos = 0; pos < 2; pos++) {
        int ozp = oz + pos * 4;
        if (ox < 34 && oy < 34 && ozp < 34) {
            int pp = ((ozp & 1) * 2 + (oy & 1)) * 2 + (ox & 1);
            int sp = ((ozp >> 1) * 17 + (oy >> 1)) * 17 + (ox >> 1);
            float r[24];
#pragma unroll
            for (int u = 0; u < 8; u++) {
#pragma unroll
                for (int i3 = 0; i3 < 3; i3++) {
                    float t = 0.f;
#pragma unroll
                    for (int v = 0; v < 4; v++)
#pragma unroll
                        for (int b = 0; b < 3; b++)
                            t = fmaf(w1[u * 12 + v * 3 + b],
                                     acc2[pos][v * 9 + b * 3 + i3], t);
                    r[u * 3 + i3] = t;
                }
            }
            float4* dst = (float4*)(g_v + (size_t)((n * 8 + pp) * 4913 + sp) * 24);
#pragma unroll
            for (int j = 0; j < 6; j++) dst[j] = ((float4*)r)[j];
        }
    }
}

// conv2: v (24ch) + on-the-fly tensor product -> da/db -> y[16]; BN stats.
// Accumulators packed across adjacent u (u=2up lo, u=2up+1 hi).
// Block tile: 8(ox) x 4(oy) x 4(oz) = 128 positions, 1/thread.
__global__ __launch_bounds__(128) void k_conv2(const float* __restrict__ b2a,
                                               const float* __restrict__ b2b,
                                               const float* __restrict__ w2a_g,
                                               const float* __restrict__ w2b_g) {
    __shared__ float shc[TAPS * 32];  // [tap][0..8=A, 9..11 pad, 12..29=sym B, 30..31 pad]
    __shared__ float w2a[384];
    __shared__ float w2b[384];
    int tid = threadIdx.x;
    for (int i = tid; i < TAPS * 32; i += 128) {
        int tap = i >> 5, j = i & 31;
        float v = 0.f;
        if (j < 9) {
            v = b2a[j * TAPS + tap];
        } else if (j >= 12 && j < 30) {
            int r = j - 12, b = r / 6, p = r % 6;
            if (p < 3)       v = b2b[(b * 9 + p * 4) * TAPS + tap];
            else if (p == 3) v = b2b[(b * 9 + 1) * TAPS + tap] + b2b[(b * 9 + 3) * TAPS + tap];
            else if (p == 4) v = b2b[(b * 9 + 2) * TAPS + tap] + b2b[(b * 9 + 6) * TAPS + tap];
            else             v = b2b[(b * 9 + 5) * TAPS + tap] + b2b[(b * 9 + 7) * TAPS + tap];
        }
        shc[i] = v;
    }
    for (int i = tid; i < 384; i += 128) { w2a[i] = w2a_g[i]; w2b[i] = w2b_g[i]; }
    __syncthreads();

    int bx = blockIdx.x;                   // grid.x = 3(x)*5(y)*5(z) = 75
    int txi = bx % 3, tyi = (bx / 3) % 5, tzi = bx / 15;
    int n = blockIdx.y;
    int lx = tid & 7, ly = (tid >> 3) & 3, lzt = tid >> 5;
    int ox = txi * 8 + lx, oy = tyi * 4 + ly, oz = tzi * 4 + lzt;

    ull DA[12], DB[12];                    // [up][b]
#pragma unroll
    for (int i = 0; i < 12; i++) { DA[i] = 0ULL; DB[i] = 0ULL; }

    const float4* zb = (const float4*)g_zero;
    int bxx = 2 * ox - 5, byy = 2 * oy - 5, bzz = 2 * oz - 5;
    for (int kz = 0; kz < 7; kz++) {
        int iz = bzz + kz;
        int pz = iz & 1, z2 = iz >> 1;
        bool vz = (unsigned)z2 < 17u;
        for (int ky = 0; ky < 7; ky++) {
            int iy = byy + ky;
            int py = iy & 1, y2 = iy >> 1;
            bool vy = (unsigned)y2 < 17u;
            int tapzy = (kz * 7 + ky) * 7;
#pragma unroll
            for (int kx = 0; kx < 7; kx++) {
                int ix = bxx + kx;
                int px = ix & 1, x2 = ix >> 1;
                bool vv = vz && vy && ((unsigned)x2 < 17u);
                int tap = tapzy + kx;
                float cr[32];
                const float4* sc4 = (const float4*)(shc + tap * 32);
#pragma unroll
                for (int j = 0; j < 8; j++) ((float4*)cr)[j] = sc4[j];
                int pp = ((n * 2 + pz) * 2 + py) * 2 + px;
                const float4* bp = (const float4*)g_v
                    + (size_t)(pp * 4913 + ((z2 * 17 + y2) * 17 + x2)) * 6;
                const float4* src = vv ? bp : zb;
                float4 v4[6];
#pragma unroll
                for (int j = 0; j < 6; j++) v4[j] = src[j];
                const float* va = (const float*)v4;
                ull ca[9], cw[18];
#pragma unroll
                for (int f = 0; f < 9; f++)  ca[f] = pk(cr[f], cr[f]);
#pragma unroll
                for (int f = 0; f < 18; f++) cw[f] = pk(cr[12 + f], cr[12 + f]);
#pragma unroll
                for (int up = 0; up < 4; up++) {
                    ull v0 = pk(va[up * 6 + 0], va[up * 6 + 3]);
                    ull v1 = pk(va[up * 6 + 1], va[up * 6 + 4]);
                    ull v2 = pk(va[up * 6 + 2], va[up * 6 + 5]);
#pragma unroll
                    for (int b = 0; b < 3; b++) {
                        fma2(DA[up * 3 + b], v0, ca[b * 3 + 0]);
                        fma2(DA[up * 3 + b], v1, ca[b * 3 + 1]);
                        fma2(DA[up * 3 + b], v2, ca[b * 3 + 2]);
                    }
                    ull p00 = mul2(v0, v0), p11 = mul2(v1, v1), p22 = mul2(v2, v2);
                    ull p01 = mul2(v0, v1), p02 = mul2(v0, v2), p12 = mul2(v1, v2);
#pragma unroll
                    for (int b = 0; b < 3; b++) {
                        fma2(DB[up * 3 + b], p00, cw[b * 6 + 0]);
                        fma2(DB[up * 3 + b], p11, cw[b * 6 + 1]);
                        fma2(DB[up * 3 + b], p22, cw[b * 6 + 2]);
                        fma2(DB[up * 3 + b], p01, cw[b * 6 + 3]);
                        fma2(DB[up * 3 + b], p02, cw[b * 6 + 4]);
                        fma2(DB[up * 3 + b], p12, cw[b * 6 + 5]);
                    }
                }
            }
        }
    }

    float da[24], db[24];
#pragma unroll
    for (int up = 0; up < 4; up++)
#pragma unroll
        for (int b = 0; b < 3; b++) {
            unpk(DA[up * 3 + b], da[up * 6 + b], da[up * 6 + 3 + b]);
            unpk(DB[up * 3 + b], db[up * 6 + b], db[up * 6 + 3 + b]);
        }

    bool valid = (ox < 19) && (oy < 19) && (oz < 19);
    float yv[16];
#pragma unroll
    for (int o = 0; o < 16; o++) {
        float r = 0.f;
#pragma unroll
        for (int u = 0; u < 8; u++)
#pragma unroll
            for (int b = 0; b < 3; b++) {
                r = fmaf(w2a[(o * 8 + u) * 3 + b], da[u * 3 + b], r);
                r = fmaf(w2b[(o * 8 + u) * 3 + b], db[u * 3 + b], r);
            }
        yv[o] = r;
    }
    if (valid) {
        size_t base = (size_t)(n * 16) * 6859 + (oz * 19 + oy) * 19 + ox;
#pragma unroll
        for (int o = 0; o < 16; o++) g_y[base + o * 6859] = yv[o];
    }
#pragma unroll
    for (int o = 0; o < 16; o++) {
        float sv = valid ? yv[o] : 0.f;
        float sq = sv * sv;
#pragma unroll
        for (int off = 16; off > 0; off >>= 1) {
            sv += __shfl_xor_sync(0xffffffffu, sv, off);
            sq += __shfl_xor_sync(0xffffffffu, sq, off);
        }
        if ((tid & 31) == 0) {
            atomicAdd(&g_sum[o], sv);
            atomicAdd(&g_sumsq[o], sq);
        }
    }
}

__global__ void k_fin(const float* __restrict__ gamma, const float* __restrict__ beta,
                      const float* __restrict__ bias, float* __restrict__ out) {
    int i = blockIdx.x * 256 + threadIdx.x;        // exactly 16*16*6859 = 6859 blocks
    int o = (i / 6859) & 15;
    const float invN = 1.f / 109744.f;             // 16 * 19^3
    float mean = g_sum[o] * invN;
    float var = g_sumsq[o] * invN - mean * mean;
    float r = rsqrtf(var + 1e-5f);
    float v = (g_y[i] - mean) * r * gamma[o] + beta[o] + bias[o];
    out[i] = v > 0.f ? v : 0.f;
}

extern "C" void kernel_launch(void* const* d_in, const int* in_sizes, int n_in,
                              void* d_out, int out_size) {
    const float* s     = (const float*)d_in[0];
    const float* basis1= (const float*)d_in[1];
    const float* W1    = (const float*)d_in[2];
    const float* b2a   = (const float*)d_in[3];
    const float* b2b   = (const float*)d_in[4];
    const float* W2a   = (const float*)d_in[5];
    const float* W2b   = (const float*)d_in[6];
    const float* gamma = (const float*)d_in[7];
    const float* beta  = (const float*)d_in[8];
    const float* bias  = (const float*)d_in[9];

    k_zero<<<1, 32>>>();
    k_split<<<65536, 256>>>(s);                     // 2^24 / 256
    k_conv1<<<dim3(225, 16), 128>>>(basis1, W1);
    k_conv2<<<dim3(75, 16), 128>>>(b2a, b2b, W2a, W2b);
    k_fin<<<6859, 256>>>(gamma, beta, bias, (float*)d_out);
}

// round 7
// speedup vs baseline: 1.2284x; 1.2284x over previous
#include <cuda_runtime.h>

#define TAPS 343
typedef unsigned long long ull;

// phase-split s, channel-interleaved: [n][pz][py][px][32][32][32][c4]  (64 MB)
__device__ float g_s[16*8*32*32*32*4];
// phase-split v, channel-interleaved: [n][pz][py][px][17][17][17][c24] (60.4 MB)
__device__ float g_v[16*8*17*17*17*24];
// y pre-BN: [n][16][19][19][19] (7 MB)
__device__ float g_y[16*16*19*19*19];
__device__ float g_sum[16];
__device__ float g_sumsq[16];
__device__ float g_zero[32];   // zero-initialized guard for OOB taps (never written)

__device__ __forceinline__ ull pk(float lo, float hi) {
    ull r; asm("mov.b64 %0,{%1,%2};" : "=l"(r) : "f"(lo), "f"(hi)); return r;
}
__device__ __forceinline__ void unpk(ull v, float& lo, float& hi) {
    asm("mov.b64 {%0,%1},%2;" : "=f"(lo), "=f"(hi) : "l"(v));
}
__device__ __forceinline__ void fma2(ull& d, ull a, ull b) {
    asm("fma.rn.f32x2 %0,%1,%2,%0;" : "+l"(d) : "l"(a), "l"(b));
}
__device__ __forceinline__ ull mul2(ull a, ull b) {
    ull r; asm("mul.rn.f32x2 %0,%1,%2;" : "=l"(r) : "l"(a), "l"(b)); return r;
}

__global__ void k_zero() {
    int i = threadIdx.x;
    if (i < 16) { g_sum[i] = 0.f; g_sumsq[i] = 0.f; }
}

// repack s (NCDHW 64^3) into parity-split channel-interleaved layout.
__global__ void k_split(const float* __restrict__ s) {
    int i = blockIdx.x * 256 + threadIdx.x;          // 2^24 total
    int x = i & 63;
    int y = (i >> 6) & 63;
    int z = (i >> 12) & 63;
    int c = (i >> 18) & 3;
    int n = i >> 20;
    int pp = (((n * 2 + (z & 1)) * 2 + (y & 1)) * 2 + (x & 1));
    int sp = ((z >> 1) * 32 + (y >> 1)) * 32 + (x >> 1);
    g_s[(pp * 32768 + sp) * 4 + c] = s[i];
}

// conv1: s[4ch] -> 36 basis responses -> mix W1 -> v[24ch] interleaved.
// Scalar FFMA (f32x2 gave no throughput: FLOP-neutral), pointer-select guard.
// Block tile: 8(ox) x 4(oy) x 8(oz); 128 threads, 2 oz positions per thread.
__global__ __launch_bounds__(128) void k_conv1(const float* __restrict__ basis1,
                                               const float* __restrict__ W1) {
    __shared__ float kb[TAPS * 12];   // [tap][f=0..8, pad 3]
    __shared__ float w1[96];
    int tid = threadIdx.x;
    for (int i = tid; i < TAPS * 12; i += 128) {
        int tap = i / 12, f = i % 12;
        kb[i] = (f < 9) ? basis1[f * TAPS + tap] : 0.f;
    }
    if (tid < 96) w1[tid] = W1[tid];
    __syncthreads();

    int bx = blockIdx.x;                  // grid.x = 5(x)*9(y)*5(z) = 225
    int txi = bx % 5, tyi = (bx / 5) % 9, tzi = bx / 45;
    int n = blockIdx.y;
    int lx = tid & 7, ly = (tid >> 3) & 3, lz = tid >> 5;
    int ox = txi * 8 + lx, oy = tyi * 4 + ly, oz = tzi * 8 + lz;

    float acc[72];
#pragma unroll
    for (int i = 0; i < 72; i++) acc[i] = 0.f;

    const float4* zb = (const float4*)g_zero;
    int bxx = 2 * ox - 5, byy = 2 * oy - 5, bzz = 2 * oz - 5;
    for (int kz = 0; kz < 7; kz++) {
        int iz = bzz + kz;
        int pz = iz & 1, z2 = iz >> 1;
        bool vzA = (unsigned)z2 < 32u;
        bool vzB = (unsigned)(z2 + 4) < 32u;
        for (int ky = 0; ky < 7; ky++) {
            int iy = byy + ky;
            int py = iy & 1, y2 = iy >> 1;
            bool vy = (unsigned)y2 < 32u;
            int tapzy = (kz * 7 + ky) * 7;
#pragma unroll
            for (int kx = 0; kx < 7; kx++) {
                int ix = bxx + kx;
                int px = ix & 1, x2 = ix >> 1;
                bool vx = (unsigned)x2 < 32u;
                int tap = tapzy + kx;
                float kr[12];
                const float4* kb4 = (const float4*)(kb + tap * 12);
                ((float4*)kr)[0] = kb4[0];
                ((float4*)kr)[1] = kb4[1];
                ((float4*)kr)[2] = kb4[2];
                int pbase = ((n * 2 + pz) * 2 + py) * 2 + px;
                int sp = (z2 * 32 + y2) * 32 + x2;
                const float4* pS = (const float4*)g_s + (pbase * 32768 + sp);
                const float4* pA = (vzA && vy && vx) ? pS        : zb;
                const float4* pB = (vzB && vy && vx) ? pS + 4096 : zb;
                float4 fA = *pA;
                float4 fB = *pB;
                float sa[4] = {fA.x, fA.y, fA.z, fA.w};
                float sb[4] = {fB.x, fB.y, fB.z, fB.w};
#pragma unroll
                for (int c = 0; c < 4; c++) {
#pragma unroll
                    for (int f = 0; f < 9; f++) {
                        acc[c * 9 + f]      = fmaf(sa[c], kr[f], acc[c * 9 + f]);
                        acc[36 + c * 9 + f] = fmaf(sb[c], kr[f], acc[36 + c * 9 + f]);
                    }
                }
            }
        }
    }

    // mix (24 out = sum over v,b of W1 * basis response) and store interleaved v
#pragma unroll
    for (int pos = 0; pos < 2; pos++) {
        int ozp = oz + pos * 4;
        if (ox < 34 && oy < 34 && ozp < 34) {
            int pp = ((ozp & 1) * 2 + (oy & 1)) * 2 + (ox & 1);
            int sp = ((ozp >> 1) * 17 + (oy >> 1)) * 17 + (ox >> 1);
            float r[24];
#pragma unroll
            for (int u = 0; u < 8; u++) {
#pragma unroll
                for (int i3 = 0; i3 < 3; i3++) {
                    float t = 0.f;
#pragma unroll
                    for (int v = 0; v < 4; v++)
#pragma unroll
                        for (int b = 0; b < 3; b++)
                            t = fmaf(w1[u * 12 + v * 3 + b],
                                     acc[pos * 36 + v * 9 + b * 3 + i3], t);
                    r[u * 3 + i3] = t;
                }
            }
            float4* dst = (float4*)(g_v + (size_t)((n * 8 + pp) * 4913 + sp) * 24);
#pragma unroll
            for (int j = 0; j < 6; j++) dst[j] = ((float4*)r)[j];
        }
    }
}

// conv2: v (24ch) + on-the-fly tensor product -> da/db -> y[16]; BN stats.
// Accumulators packed across adjacent u (u=2up lo, u=2up+1 hi), f32x2.
// __launch_bounds__(128,4): target <=128 regs for 4 CTAs/SM occupancy.
// Block tile: 8(ox) x 4(oy) x 4(oz) = 128 positions, 1/thread.
__global__ __launch_bounds__(128, 4) void k_conv2(const float* __restrict__ b2a,
                                                  const float* __restrict__ b2b,
                                                  const float* __restrict__ w2a_g,
                                                  const float* __restrict__ w2b_g) {
    __shared__ float shc[TAPS * 32];  // [tap][0..8=A, 9..11 pad, 12..29=sym B, 30..31 pad]
    __shared__ float w2a[384];
    __shared__ float w2b[384];
    int tid = threadIdx.x;
    for (int i = tid; i < TAPS * 32; i += 128) {
        int tap = i >> 5, j = i & 31;
        float v = 0.f;
        if (j < 9) {
            v = b2a[j * TAPS + tap];
        } else if (j >= 12 && j < 30) {
            int r = j - 12, b = r / 6, p = r % 6;
            if (p < 3)       v = b2b[(b * 9 + p * 4) * TAPS + tap];
            else if (p == 3) v = b2b[(b * 9 + 1) * TAPS + tap] + b2b[(b * 9 + 3) * TAPS + tap];
            else if (p == 4) v = b2b[(b * 9 + 2) * TAPS + tap] + b2b[(b * 9 + 6) * TAPS + tap];
            else             v = b2b[(b * 9 + 5) * TAPS + tap] + b2b[(b * 9 + 7) * TAPS + tap];
        }
        shc[i] = v;
    }
    for (int i = tid; i < 384; i += 128) { w2a[i] = w2a_g[i]; w2b[i] = w2b_g[i]; }
    __syncthreads();

    int bx = blockIdx.x;                   // grid.x = 3(x)*5(y)*5(z) = 75
    int txi = bx % 3, tyi = (bx / 3) % 5, tzi = bx / 15;
    int n = blockIdx.y;
    int lx = tid & 7, ly = (tid >> 3) & 3, lzt = tid >> 5;
    int ox = txi * 8 + lx, oy = tyi * 4 + ly, oz = tzi * 4 + lzt;

    ull DA[12], DB[12];                    // [up][b]
#pragma unroll
    for (int i = 0; i < 12; i++) { DA[i] = 0ULL; DB[i] = 0ULL; }

    const float4* zb = (const float4*)g_zero;
    int bxx = 2 * ox - 5, byy = 2 * oy - 5, bzz = 2 * oz - 5;
    for (int kz = 0; kz < 7; kz++) {
        int iz = bzz + kz;
        int pz = iz & 1, z2 = iz >> 1;
        bool vz = (unsigned)z2 < 17u;
        for (int ky = 0; ky < 7; ky++) {
            int iy = byy + ky;
            int py = iy & 1, y2 = iy >> 1;
            bool vy = (unsigned)y2 < 17u;
            int tapzy = (kz * 7 + ky) * 7;
#pragma unroll
            for (int kx = 0; kx < 7; kx++) {
                int ix = bxx + kx;
                int px = ix & 1, x2 = ix >> 1;
                bool vv = vz && vy && ((unsigned)x2 < 17u);
                int tap = tapzy + kx;
                float cr[32];
                const float4* sc4 = (const float4*)(shc + tap * 32);
#pragma unroll
                for (int j = 0; j < 8; j++) ((float4*)cr)[j] = sc4[j];
                int pp = ((n * 2 + pz) * 2 + py) * 2 + px;
                const float4* bp = (const float4*)g_v
                    + (size_t)(pp * 4913 + ((z2 * 17 + y2) * 17 + x2)) * 6;
                const float4* src = vv ? bp : zb;
                float4 v4[6];
#pragma unroll
                for (int j = 0; j < 6; j++) v4[j] = src[j];
                const float* va = (const float*)v4;
                ull ca[9], cw[18];
#pragma unroll
                for (int f = 0; f < 9; f++)  ca[f] = pk(cr[f], cr[f]);
#pragma unroll
                for (int f = 0; f < 18; f++) cw[f] = pk(cr[12 + f], cr[12 + f]);
#pragma unroll
                for (int up = 0; up < 4; up++) {
                    ull v0 = pk(va[up * 6 + 0], va[up * 6 + 3]);
                    ull v1 = pk(va[up * 6 + 1], va[up * 6 + 4]);
                    ull v2 = pk(va[up * 6 + 2], va[up * 6 + 5]);
#pragma unroll
                    for (int b = 0; b < 3; b++) {
                        fma2(DA[up * 3 + b], v0, ca[b * 3 + 0]);
                        fma2(DA[up * 3 + b], v1, ca[b * 3 + 1]);
                        fma2(DA[up * 3 + b], v2, ca[b * 3 + 2]);
                    }
                    ull p00 = mul2(v0, v0), p11 = mul2(v1, v1), p22 = mul2(v2, v2);
                    ull p01 = mul2(v0, v1), p02 = mul2(v0, v2), p12 = mul2(v1, v2);
#pragma unroll
                    for (int b = 0; b < 3; b++) {
                        fma2(DB[up * 3 + b], p00, cw[b * 6 + 0]);
                        fma2(DB[up * 3 + b], p11, cw[b * 6 + 1]);
                        fma2(DB[up * 3 + b], p22, cw[b * 6 + 2]);
                        fma2(DB[up * 3 + b], p01, cw[b * 6 + 3]);
                        fma2(DB[up * 3 + b], p02, cw[b * 6 + 4]);
                        fma2(DB[up * 3 + b], p12, cw[b * 6 + 5]);
                    }
                }
            }
        }
    }

    float da[24], db[24];
#pragma unroll
    for (int up = 0; up < 4; up++)
#pragma unroll
        for (int b = 0; b < 3; b++) {
            unpk(DA[up * 3 + b], da[up * 6 + b], da[up * 6 + 3 + b]);
            unpk(DB[up * 3 + b], db[up * 6 + b], db[up * 6 + 3 + b]);
        }

    bool valid = (ox < 19) && (oy < 19) && (oz < 19);
    float yv[16];
#pragma unroll
    for (int o = 0; o < 16; o++) {
        float r = 0.f;
#pragma unroll
        for (int u = 0; u < 8; u++)
#pragma unroll
            for (int b = 0; b < 3; b++) {
                r = fmaf(w2a[(o * 8 + u) * 3 + b], da[u * 3 + b], r);
                r = fmaf(w2b[(o * 8 + u) * 3 + b], db[u * 3 + b], r);
            }
        yv[o] = r;
    }
    if (valid) {
        size_t base = (size_t)(n * 16) * 6859 + (oz * 19 + oy) * 19 + ox;
#pragma unroll
        for (int o = 0; o < 16; o++) g_y[base + o * 6859] = yv[o];
    }
#pragma unroll
    for (int o = 0; o < 16; o++) {
        float sv = valid ? yv[o] : 0.f;
        float sq = sv * sv;
#pragma unroll
        for (int off = 16; off > 0; off >>= 1) {
            sv += __shfl_xor_sync(0xffffffffu, sv, off);
            sq += __shfl_xor_sync(0xffffffffu, sq, off);
        }
        if ((tid & 31) == 0) {
            atomicAdd(&g_sum[o], sv);
            atomicAdd(&g_sumsq[o], sq);
        }
    }
}

__global__ void k_fin(const float* __restrict__ gamma, const float* __restrict__ beta,
                      const float* __restrict__ bias, float* __restrict__ out) {
    int i = blockIdx.x * 256 + threadIdx.x;        // exactly 16*16*6859 = 6859 blocks
    int o = (i / 6859) & 15;
    const float invN = 1.f / 109744.f;             // 16 * 19^3
    float mean = g_sum[o] * invN;
    float var = g_sumsq[o] * invN - mean * mean;
    float r = rsqrtf(var + 1e-5f);
    float v = (g_y[i] - mean) * r * gamma[o] + beta[o] + bias[o];
    out[i] = v > 0.f ? v : 0.f;
}

extern "C" void kernel_launch(void* const* d_in, const int* in_sizes, int n_in,
                              void* d_out, int out_size) {
    const float* s     = (const float*)d_in[0];
    const float* basis1= (const float*)d_in[1];
    const float* W1    = (const float*)d_in[2];
    const float* b2a   = (const float*)d_in[3];
    const float* b2b   = (const float*)d_in[4];
    const float* W2a   = (const float*)d_in[5];
    const float* W2b   = (const float*)d_in[6];
    const float* gamma = (const float*)d_in[7];
    const float* beta  = (const float*)d_in[8];
    const float* bias  = (const float*)d_in[9];

    k_zero<<<1, 32>>>();
    k_split<<<65536, 256>>>(s);                     // 2^24 / 256
    k_conv1<<<dim3(225, 16), 128>>>(basis1, W1);
    k_conv2<<<dim3(75, 16), 128>>>(b2a, b2b, W2a, W2b);
    k_fin<<<6859, 256>>>(gamma, beta, bias, (float*)d_out);
}